// round 1
// baseline (speedup 1.0000x reference)
#include <cuda_runtime.h>
#include <math.h>

// Problem constants
#define BB     2
#define HH     16
#define TQ     2048
#define TPAST  2048
#define TKV    4096
#define DKH    64
#define DM     1024
#define MROWS  (BB*TQ)          // 4096

#define OUT_O_ELEMS  ((size_t)MROWS*DM)            // 4,194,304
#define OUT_KV_ELEMS ((size_t)BB*HH*TKV*DKH)       // 8,388,608
#define OUT_TOTAL    (OUT_O_ELEMS + 2*OUT_KV_ELEMS)

// Scratch (device globals; allocation inside kernel_launch is forbidden)
__device__ float g_Q[BB*HH*TQ*DKH];      // Q in [B,H,TQ,DK] layout, pre-scaled
__device__ float g_attn[MROWS*DM];       // attention output in [B*TQ, D] layout
__device__ float g_K[BB*HH*TKV*DKH];     // fallback KV buffers if d_out is small
__device__ float g_V[BB*HH*TKV*DKH];

// ---------------------------------------------------------------------------
// Copy past_K / past_V into the concat destination [B,H,TKV,DK] (first TPAST rows)
// ---------------------------------------------------------------------------
__global__ void copy_past_kernel(const float* __restrict__ pk,
                                 const float* __restrict__ pv,
                                 float* __restrict__ outK,
                                 float* __restrict__ outV) {
    int idx = blockIdx.x * blockDim.x + threadIdx.x;   // float4 index
    const int total = BB*HH*TPAST*DKH/4;
    if (idx >= total) return;
    const int per_bh = TPAST*DKH/4;                    // 32768
    int bh  = idx / per_bh;
    int rem = idx - bh*per_bh;
    const float4* pk4 = (const float4*)pk;
    const float4* pv4 = (const float4*)pv;
    ((float4*)outK)[(size_t)bh*(TKV*DKH/4) + rem] = pk4[idx];
    ((float4*)outV)[(size_t)bh*(TKV*DKH/4) + rem] = pv4[idx];
}

// ---------------------------------------------------------------------------
// NT GEMM: C[m,n] = sum_k A[m,k]*W[n,k] + bias[n]
// M=4096, N=1024, K=1024 fixed. 64x64 tile, BK=16, 256 threads, 4x4/thread.
// Epilogue scatter modes:
//   0: Q head layout  [B,H,TQ,DK]
//   1: KV concat slot [B,H,TKV,DK] at time TPAST+t
//   2: plain row-major [M,N]
// ---------------------------------------------------------------------------
__global__ void gemm_nt_kernel(const float* __restrict__ A,
                               const float* __restrict__ W,
                               const float* __restrict__ bias,
                               float* __restrict__ Cout,
                               int mode) {
    __shared__ float As[16][68];
    __shared__ float Ws[16][68];

    const int tid = threadIdx.x;
    const int tx  = tid & 15;
    const int ty  = tid >> 4;
    const int m0  = blockIdx.y * 64;
    const int n0  = blockIdx.x * 64;

    const int lr = tid >> 2;          // 0..63 (tile row)
    const int lk = (tid & 3) * 4;     // 0,4,8,12 (k offset)

    float acc[4][4];
#pragma unroll
    for (int i = 0; i < 4; i++)
#pragma unroll
        for (int j = 0; j < 4; j++) acc[i][j] = 0.f;

    const float* Arow = A + (size_t)(m0 + lr) * DM;
    const float* Wrow = W + (size_t)(n0 + lr) * DM;

    for (int k0 = 0; k0 < DM; k0 += 16) {
        float4 av = *(const float4*)&Arow[k0 + lk];
        float4 wv = *(const float4*)&Wrow[k0 + lk];
        __syncthreads();
        As[lk+0][lr] = av.x; As[lk+1][lr] = av.y; As[lk+2][lr] = av.z; As[lk+3][lr] = av.w;
        Ws[lk+0][lr] = wv.x; Ws[lk+1][lr] = wv.y; Ws[lk+2][lr] = wv.z; Ws[lk+3][lr] = wv.w;
        __syncthreads();
#pragma unroll
        for (int kk = 0; kk < 16; kk++) {
            float4 a = *(const float4*)&As[kk][ty*4];
            float4 w = *(const float4*)&Ws[kk][tx*4];
            acc[0][0] += a.x*w.x; acc[0][1] += a.x*w.y; acc[0][2] += a.x*w.z; acc[0][3] += a.x*w.w;
            acc[1][0] += a.y*w.x; acc[1][1] += a.y*w.y; acc[1][2] += a.y*w.z; acc[1][3] += a.y*w.w;
            acc[2][0] += a.z*w.x; acc[2][1] += a.z*w.y; acc[2][2] += a.z*w.z; acc[2][3] += a.z*w.w;
            acc[3][0] += a.w*w.x; acc[3][1] += a.w*w.y; acc[3][2] += a.w*w.z; acc[3][3] += a.w*w.w;
        }
    }

#pragma unroll
    for (int i = 0; i < 4; i++) {
        int m = m0 + ty*4 + i;
        int b = m / TQ, t = m - b*TQ;
#pragma unroll
        for (int j = 0; j < 4; j++) {
            int n = n0 + tx*4 + j;
            float v = acc[i][j] + bias[n];
            int h = n >> 6, d = n & 63;
            if (mode == 0) {
                Cout[(((size_t)(b*HH + h)*TQ + t) << 6) + d] = v;
            } else if (mode == 1) {
                Cout[(((size_t)(b*HH + h)*TKV + TPAST + t) << 6) + d] = v;
            } else {
                Cout[(size_t)m*DM + n] = v;
            }
        }
    }
}

// ---------------------------------------------------------------------------
// Flash attention, fp32. One CTA per (b, h, 64-row q tile). Causal mask is
// analytic: q row i attends kv j <= TPAST + i. Full tiles up to the diagonal,
// then exactly one triangular tile.
// ---------------------------------------------------------------------------
__global__ void flash_attn_kernel(const float* __restrict__ Kc,
                                  const float* __restrict__ Vc) {
    extern __shared__ float sm[];
    float (*Qs)[68] = (float(*)[68])sm;        // [d][q]  (pre-scaled by 1/8)
    float (*Ks)[68] = Qs + 64;                 // [d][j]
    float (*Vs)[68] = Ks + 64;                 // [j][d]
    float (*Ps)[68] = Vs + 64;                 // [j][q]

    const int tid = threadIdx.x;
    const int tx  = tid & 15;
    const int ty  = tid >> 4;
    const int q0  = blockIdx.x * 64;
    const int h   = blockIdx.y;
    const int b   = blockIdx.z;

    const float* Qptr = g_Q + (((size_t)(b*HH + h)*TQ + q0) << 6);
    const float* Kbh  = Kc + (((size_t)(b*HH + h)*TKV) << 6);
    const float* Vbh  = Vc + (((size_t)(b*HH + h)*TKV) << 6);

    // Load Q tile -> Qs[d][q], scaled by 1/sqrt(64) = 0.125
    {
        int q  = tid >> 2;
        int d4 = (tid & 3) * 4;
#pragma unroll
        for (int c = 0; c < 4; c++) {
            int d = d4 + c*16;
            float4 qv = *(const float4*)&Qptr[(q << 6) + d];
            Qs[d+0][q] = qv.x * 0.125f;
            Qs[d+1][q] = qv.y * 0.125f;
            Qs[d+2][q] = qv.z * 0.125f;
            Qs[d+3][q] = qv.w * 0.125f;
        }
    }

    float o[4][4];
    float m_i[4], l_i[4];
#pragma unroll
    for (int i = 0; i < 4; i++) {
        m_i[i] = -1e30f; l_i[i] = 0.f;
#pragma unroll
        for (int j = 0; j < 4; j++) o[i][j] = 0.f;
    }

    const int nf = (TPAST + q0) >> 6;   // index of the triangular (last) tile

    for (int t = 0; t <= nf; t++) {
        const int kv0 = t * 64;
        // Load K/V tiles into registers (overlaps previous iteration's PV)
        int j  = tid >> 2;
        int d4 = (tid & 3) * 4;
        float4 kr[4], vr[4];
#pragma unroll
        for (int c = 0; c < 4; c++) {
            int d = d4 + c*16;
            kr[c] = *(const float4*)&Kbh[((size_t)(kv0 + j) << 6) + d];
            vr[c] = *(const float4*)&Vbh[((size_t)(kv0 + j) << 6) + d];
        }
        __syncthreads();   // previous PV done: safe to overwrite Ks/Vs
#pragma unroll
        for (int c = 0; c < 4; c++) {
            int d = d4 + c*16;
            Ks[d+0][j] = kr[c].x; Ks[d+1][j] = kr[c].y;
            Ks[d+2][j] = kr[c].z; Ks[d+3][j] = kr[c].w;
            *(float4*)&Vs[j][d] = vr[c];
        }
        __syncthreads();

        // S = (Q/8) @ K^T  (64x64x64)
        float s[4][4];
#pragma unroll
        for (int i = 0; i < 4; i++)
#pragma unroll
            for (int jj = 0; jj < 4; jj++) s[i][jj] = 0.f;
#pragma unroll 16
        for (int d = 0; d < 64; d++) {
            float4 a = *(const float4*)&Qs[d][ty*4];
            float4 k = *(const float4*)&Ks[d][tx*4];
            s[0][0] += a.x*k.x; s[0][1] += a.x*k.y; s[0][2] += a.x*k.z; s[0][3] += a.x*k.w;
            s[1][0] += a.y*k.x; s[1][1] += a.y*k.y; s[1][2] += a.y*k.z; s[1][3] += a.y*k.w;
            s[2][0] += a.z*k.x; s[2][1] += a.z*k.y; s[2][2] += a.z*k.z; s[2][3] += a.z*k.w;
            s[3][0] += a.w*k.x; s[3][1] += a.w*k.y; s[3][2] += a.w*k.z; s[3][3] += a.w*k.w;
        }

        if (t == nf) {  // triangular tile: col c allowed iff c <= row r
#pragma unroll
            for (int i = 0; i < 4; i++)
#pragma unroll
                for (int jj = 0; jj < 4; jj++)
                    if (tx*4 + jj > ty*4 + i) s[i][jj] = -1e30f;
        }

        // Online softmax (rows distributed: 16 lanes with same ty hold one row)
#pragma unroll
        for (int i = 0; i < 4; i++) {
            float mx = fmaxf(fmaxf(s[i][0], s[i][1]), fmaxf(s[i][2], s[i][3]));
#pragma unroll
            for (int off = 8; off > 0; off >>= 1)
                mx = fmaxf(mx, __shfl_xor_sync(0xffffffffu, mx, off));
            float mnew  = fmaxf(m_i[i], mx);
            float alpha = __expf(m_i[i] - mnew);
            m_i[i] = mnew;
            float rs = 0.f;
#pragma unroll
            for (int jj = 0; jj < 4; jj++) {
                s[i][jj] = __expf(s[i][jj] - mnew);
                rs += s[i][jj];
            }
#pragma unroll
            for (int off = 8; off > 0; off >>= 1)
                rs += __shfl_xor_sync(0xffffffffu, rs, off);
            l_i[i] = l_i[i] * alpha + rs;
#pragma unroll
            for (int jj = 0; jj < 4; jj++) o[i][jj] *= alpha;
        }

        // Store P transposed: Ps[j][q]
#pragma unroll
        for (int i = 0; i < 4; i++)
#pragma unroll
            for (int jj = 0; jj < 4; jj++)
                Ps[tx*4 + jj][ty*4 + i] = s[i][jj];
        __syncthreads();

        // O += P @ V  (64x64x64)
#pragma unroll 16
        for (int k = 0; k < 64; k++) {
            float4 p = *(const float4*)&Ps[k][ty*4];
            float4 v = *(const float4*)&Vs[k][tx*4];
            o[0][0] += p.x*v.x; o[0][1] += p.x*v.y; o[0][2] += p.x*v.z; o[0][3] += p.x*v.w;
            o[1][0] += p.y*v.x; o[1][1] += p.y*v.y; o[1][2] += p.y*v.z; o[1][3] += p.y*v.w;
            o[2][0] += p.z*v.x; o[2][1] += p.z*v.y; o[2][2] += p.z*v.z; o[2][3] += p.z*v.w;
            o[3][0] += p.w*v.x; o[3][1] += p.w*v.y; o[3][2] += p.w*v.z; o[3][3] += p.w*v.w;
        }
    }

    // Normalize and write to g_attn in [B*TQ, D] layout
#pragma unroll
    for (int i = 0; i < 4; i++) {
        float inv = 1.0f / l_i[i];
        int qg = q0 + ty*4 + i;
        float* dst = g_attn + (size_t)(b*TQ + qg)*DM + (h << 6) + tx*4;
        dst[0] = o[i][0]*inv; dst[1] = o[i][1]*inv;
        dst[2] = o[i][2]*inv; dst[3] = o[i][3]*inv;
    }
}

// ---------------------------------------------------------------------------
extern "C" void kernel_launch(void* const* d_in, const int* in_sizes, int n_in,
                              void* d_out, int out_size) {
    const float* query  = (const float*)d_in[0];
    const float* key    = (const float*)d_in[1];
    const float* value  = (const float*)d_in[2];
    const float* past_K = (const float*)d_in[3];
    const float* past_V = (const float*)d_in[4];
    // d_in[5] = mask (causal; computed analytically, not read)
    const float* Wq = (const float*)d_in[6];
    const float* bq = (const float*)d_in[7];
    const float* Wk = (const float*)d_in[8];
    const float* bk = (const float*)d_in[9];
    const float* Wv = (const float*)d_in[10];
    const float* bv = (const float*)d_in[11];
    const float* Wo = (const float*)d_in[12];
    const float* bo = (const float*)d_in[13];

    float* out = (float*)d_out;

    // Resolve scratch symbol addresses (host API, not a stream op: capture-safe)
    float *gQ, *gAttn, *gK, *gV;
    cudaGetSymbolAddress((void**)&gQ,    g_Q);
    cudaGetSymbolAddress((void**)&gAttn, g_attn);
    cudaGetSymbolAddress((void**)&gK,    g_K);
    cudaGetSymbolAddress((void**)&gV,    g_V);

    // Output layout: assume tuple concat (out, K, V); fall back to scratch KV
    float* outK;
    float* outV;
    if ((size_t)out_size >= OUT_TOTAL) {
        outK = out + OUT_O_ELEMS;
        outV = outK + OUT_KV_ELEMS;
    } else {
        outK = gK;
        outV = gV;
    }

    static int smem_set = 0;
    const int FLASH_SMEM = 4 * 64 * 68 * (int)sizeof(float);  // 69,632 B
    if (!smem_set) {
        cudaFuncSetAttribute(flash_attn_kernel,
                             cudaFuncAttributeMaxDynamicSharedMemorySize, FLASH_SMEM);
        smem_set = 1;
    }

    // 1. KV-cache concat (past part)
    {
        int total4 = BB*HH*TPAST*DKH/4;
        copy_past_kernel<<<(total4 + 255)/256, 256>>>(past_K, past_V, outK, outV);
    }

    // 2. Projections (epilogue fuses head reshape + cache concat)
    dim3 gg(DM/64, MROWS/64);
    gemm_nt_kernel<<<gg, 256>>>(query, Wq, bq, gQ,   0);
    gemm_nt_kernel<<<gg, 256>>>(key,   Wk, bk, outK, 1);
    gemm_nt_kernel<<<gg, 256>>>(value, Wv, bv, outV, 1);

    // 3. Attention
    flash_attn_kernel<<<dim3(TQ/64, HH, BB), 256, FLASH_SMEM>>>(outK, outV);

    // 4. Output projection
    gemm_nt_kernel<<<gg, 256>>>(gAttn, Wo, bo, out, 2);
}

// round 3
// speedup vs baseline: 3.1890x; 3.1890x over previous
#include <cuda_runtime.h>
#include <stdint.h>
#include <math.h>

// Problem constants
#define BB     2
#define HH     16
#define TQ     2048
#define TPAST  2048
#define TKV    4096
#define DM     1024
#define MROWS  (BB*TQ)          // 4096

#define OUT_O_ELEMS  ((size_t)MROWS*DM)            // 4,194,304
#define OUT_KV_ELEMS ((size_t)BB*HH*TKV*64)        // 8,388,608
#define OUT_TOTAL    (OUT_O_ELEMS + 2*OUT_KV_ELEMS)

// Scratch (device globals; allocation inside kernel_launch is forbidden)
__device__ float g_Q[BB*HH*TQ*64];       // Q in [B,H,TQ,64], pre-scaled by 1/8
__device__ float g_attn[MROWS*DM];       // attention output [B*TQ, D]
__device__ float g_K[BB*HH*TKV*64];      // fallback KV if d_out small
__device__ float g_V[BB*HH*TKV*64];

// ---------------------------------------------------------------------------
// PTX helpers
// ---------------------------------------------------------------------------
__device__ __forceinline__ uint32_t f2tf(float f) {
    uint32_t u;
    asm("cvt.rna.tf32.f32 %0, %1;" : "=r"(u) : "f"(f));
    return u;
}

__device__ __forceinline__ void mma8(float* c, const uint32_t* a,
                                     uint32_t b0, uint32_t b1) {
    asm volatile(
        "mma.sync.aligned.m16n8k8.row.col.f32.tf32.tf32.f32 "
        "{%0,%1,%2,%3},{%4,%5,%6,%7},{%8,%9},{%0,%1,%2,%3};"
        : "+f"(c[0]), "+f"(c[1]), "+f"(c[2]), "+f"(c[3])
        : "r"(a[0]), "r"(a[1]), "r"(a[2]), "r"(a[3]), "r"(b0), "r"(b1));
}

__device__ __forceinline__ void cp16(uint32_t s, const void* g) {
    asm volatile("cp.async.cg.shared.global [%0], [%1], 16;" :: "r"(s), "l"(g));
}
__device__ __forceinline__ void cp_commit() { asm volatile("cp.async.commit_group;"); }
template<int N> __device__ __forceinline__ void cp_wait() {
    asm volatile("cp.async.wait_group %0;" :: "n"(N));
}

// ---------------------------------------------------------------------------
// past_K / past_V bulk copy into concat destination [B,H,TKV,64]
// ---------------------------------------------------------------------------
__global__ void copy_past_kernel(const float* __restrict__ pk,
                                 const float* __restrict__ pv,
                                 float* __restrict__ outK,
                                 float* __restrict__ outV) {
    int idx = blockIdx.x * blockDim.x + threadIdx.x;
    const int total = BB*HH*TPAST*64/4;
    if (idx >= total) return;
    const int per_bh = TPAST*64/4;
    int bh  = idx / per_bh;
    int rem = idx - bh*per_bh;
    const float4* pk4 = (const float4*)pk;
    const float4* pv4 = (const float4*)pv;
    ((float4*)outK)[(size_t)bh*(TKV*64/4) + rem] = pk4[idx];
    ((float4*)outV)[(size_t)bh*(TKV*64/4) + rem] = pv4[idx];
}

// ---------------------------------------------------------------------------
// TF32 tensor-core NT GEMM: C[m,n] = sum_k A[m,k]*W[n,k] + bias[n]
// M=4096, N=1024, K=1024. CTA tile 128x128, BK=32, 256 threads (8 warps),
// warp tile 64x32 via m16n8k8. Double-buffered cp.async, XOR-swizzled smem.
// Epilogue modes: 0 = Q head layout (also *0.125), 1 = KV concat slot,
//                 2 = plain row-major [M,N].
// ---------------------------------------------------------------------------
__global__ __launch_bounds__(256) void gemm_tf32(const float* __restrict__ A,
                                                 const float* __restrict__ W,
                                                 const float* __restrict__ bias,
                                                 float* __restrict__ C,
                                                 int mode) {
    extern __shared__ float sm[];
    // layout: Abuf0[4096] Abuf1[4096] Bbuf0[4096] Bbuf1[4096]  (128 rows x 32 k)
    const int tid  = threadIdx.x;
    const int lane = tid & 31;
    const int wid  = tid >> 5;
    const int wm   = wid & 1;           // 2 warp-rows of 64
    const int wn   = wid >> 1;          // 4 warp-cols of 32
    const int m0   = blockIdx.y * 128;
    const int n0   = blockIdx.x * 128;
    const int r    = lane >> 2;         // 0..7
    const int cq   = lane & 3;          // 0..3

    uint32_t smb = (uint32_t)__cvta_generic_to_shared(sm);

    float acc[4][4][4];
#pragma unroll
    for (int mt = 0; mt < 4; mt++)
#pragma unroll
        for (int nt = 0; nt < 4; nt++)
#pragma unroll
            for (int i = 0; i < 4; i++) acc[mt][nt][i] = 0.f;

    // ---- staging: slot = tid + p*256 -> row = slot>>3, quad = slot&7 ----
#define GEMM_STAGE(kt, buf)                                                     \
    {                                                                           \
        int k0s = (kt) * 32;                                                    \
        _Pragma("unroll")                                                       \
        for (int p = 0; p < 4; p++) {                                           \
            int slot = tid + p*256;                                             \
            int row  = slot >> 3;                                               \
            int quad = slot & 7;                                                \
            int col  = (quad*4) ^ ((row & 7) << 2);                             \
            cp16(smb + (uint32_t)(((buf)*4096 + row*32 + col) * 4),             \
                 A + (size_t)(m0 + row)*DM + k0s + quad*4);                     \
            cp16(smb + (uint32_t)((8192 + (buf)*4096 + row*32 + col) * 4),      \
                 W + (size_t)(n0 + row)*DM + k0s + quad*4);                     \
        }                                                                       \
        cp_commit();                                                            \
    }

    GEMM_STAGE(0, 0);

    for (int kt = 0; kt < 32; kt++) {
        if (kt + 1 < 32) {
            GEMM_STAGE(kt + 1, (kt + 1) & 1);
            cp_wait<1>();
        } else {
            cp_wait<0>();
        }
        __syncthreads();

        const float* Ab = sm + ((kt & 1) * 4096);
        const float* Bb = sm + 8192 + ((kt & 1) * 4096);
        const int sw = r << 2;   // (row&7)<<2, row&7 == r for all fragment rows

#pragma unroll
        for (int kc = 0; kc < 4; kc++) {
            const int k = kc*8 + cq;
            uint32_t afr[4][4], bfr[4][2];
#pragma unroll
            for (int mt = 0; mt < 4; mt++) {
                int m = wm*64 + mt*16 + r;
                afr[mt][0] = f2tf(Ab[m*32       + (k ^ sw)]);
                afr[mt][1] = f2tf(Ab[(m+8)*32   + (k ^ sw)]);
                afr[mt][2] = f2tf(Ab[m*32       + ((k+4) ^ sw)]);
                afr[mt][3] = f2tf(Ab[(m+8)*32   + ((k+4) ^ sw)]);
            }
#pragma unroll
            for (int nt = 0; nt < 4; nt++) {
                int n = wn*32 + nt*8 + r;
                bfr[nt][0] = f2tf(Bb[n*32 + (k ^ sw)]);
                bfr[nt][1] = f2tf(Bb[n*32 + ((k+4) ^ sw)]);
            }
#pragma unroll
            for (int mt = 0; mt < 4; mt++)
#pragma unroll
                for (int nt = 0; nt < 4; nt++)
                    mma8(acc[mt][nt], afr[mt], bfr[nt][0], bfr[nt][1]);
        }
        __syncthreads();
    }
#undef GEMM_STAGE

    // ---- epilogue ----
#pragma unroll
    for (int mt = 0; mt < 4; mt++) {
#pragma unroll
        for (int half = 0; half < 2; half++) {
            int m  = m0 + wm*64 + mt*16 + r + half*8;
            int bb = m / TQ;
            int tq = m - bb*TQ;
#pragma unroll
            for (int nt = 0; nt < 4; nt++) {
                int n = n0 + wn*32 + nt*8 + cq*2;
                float2 bi = *(const float2*)&bias[n];
                float v0 = acc[mt][nt][half*2 + 0] + bi.x;
                float v1 = acc[mt][nt][half*2 + 1] + bi.y;
                int h = n >> 6, d = n & 63;
                if (mode == 0) {
                    float2 o = make_float2(v0*0.125f, v1*0.125f);
                    *(float2*)&C[(((size_t)(bb*HH + h)*TQ + tq) << 6) + d] = o;
                } else if (mode == 1) {
                    float2 o = make_float2(v0, v1);
                    *(float2*)&C[(((size_t)(bb*HH + h)*TKV + TPAST + tq) << 6) + d] = o;
                } else {
                    float2 o = make_float2(v0, v1);
                    *(float2*)&C[(size_t)m*DM + n] = o;
                }
            }
        }
    }
}

// ---------------------------------------------------------------------------
// TF32 flash attention. CTA = 128 q rows x (b,h). 8 warps; warp owns 16 q rows,
// full 64-j kv tile, full d=64. Q fragments live in registers across the loop.
// K read from Ks[j][d] (stride 68), V from Vs[j][d] (stride 72) — both layouts
// feed mma B fragments directly with conflict-free banks. P restaged through
// the retired Q smem region (warp-private).
// ---------------------------------------------------------------------------
__global__ __launch_bounds__(256, 1) void flash_tf32(const float* __restrict__ Kc,
                                                     const float* __restrict__ Vc) {
    extern __shared__ float sm[];
    float* QP = sm;                 // 128 x 68 : Q staging, then P
    float* Ks = sm + 128*68;        // 64 x 68
    float* Vs = sm + 128*68 + 64*68;// 64 x 72

    const int tid  = threadIdx.x;
    const int lane = tid & 31;
    const int w    = tid >> 5;
    const int r    = lane >> 2;
    const int cq   = lane & 3;
    const int q0   = blockIdx.x * 128;
    const int h    = blockIdx.y;
    const int b    = blockIdx.z;

    const float* Qbh = g_Q + (((size_t)(b*HH + h)*TQ + q0) << 6);
    const float* Kbh = Kc + (((size_t)(b*HH + h)*TKV) << 6);
    const float* Vbh = Vc + (((size_t)(b*HH + h)*TKV) << 6);

    // ---- Q tile -> smem (raw fp32), then extract fragments to registers ----
#pragma unroll
    for (int p = 0; p < 8; p++) {
        int slot = tid + p*256;
        int row = slot >> 4, quad = slot & 15;
        float4 qv = *(const float4*)&Qbh[(row << 6) + quad*4];
        *(float4*)&QP[row*68 + quad*4] = qv;
    }
    __syncthreads();

    uint32_t qa[8][4];
    {
        int m = 16*w + r;
#pragma unroll
        for (int kc = 0; kc < 8; kc++) {
            int k = kc*8 + cq;
            qa[kc][0] = f2tf(QP[m*68 + k]);
            qa[kc][1] = f2tf(QP[(m+8)*68 + k]);
            qa[kc][2] = f2tf(QP[m*68 + k + 4]);
            qa[kc][3] = f2tf(QP[(m+8)*68 + k + 4]);
        }
    }
    __syncthreads();   // QP now reusable as P

    float o[8][4];
#pragma unroll
    for (int nt = 0; nt < 8; nt++)
#pragma unroll
        for (int i = 0; i < 4; i++) o[nt][i] = 0.f;
    float mi0 = -1e30f, mi1 = -1e30f, li0 = 0.f, li1 = 0.f;

    const int nfull  = (TPAST + q0) >> 6;   // first masked tile index
    const int ntiles = nfull + 2;

    for (int t = 0; t < ntiles; t++) {
        const int kv0 = t * 64;

        // prefetch K,V tile into registers (overlaps prior compute tail)
        float4 kr[4], vr[4];
#pragma unroll
        for (int p = 0; p < 4; p++) {
            int slot = tid + p*256;
            int row = slot >> 4, quad = slot & 15;
            size_t g = ((size_t)(kv0 + row) << 6) + quad*4;
            kr[p] = *(const float4*)&Kbh[g];
            vr[p] = *(const float4*)&Vbh[g];
        }
        __syncthreads();   // previous tile's smem reads complete
#pragma unroll
        for (int p = 0; p < 4; p++) {
            int slot = tid + p*256;
            int row = slot >> 4, quad = slot & 15;
            float4 kk = make_float4(__uint_as_float(f2tf(kr[p].x)),
                                    __uint_as_float(f2tf(kr[p].y)),
                                    __uint_as_float(f2tf(kr[p].z)),
                                    __uint_as_float(f2tf(kr[p].w)));
            float4 vv = make_float4(__uint_as_float(f2tf(vr[p].x)),
                                    __uint_as_float(f2tf(vr[p].y)),
                                    __uint_as_float(f2tf(vr[p].z)),
                                    __uint_as_float(f2tf(vr[p].w)));
            *(float4*)&Ks[row*68 + quad*4] = kk;
            *(float4*)&Vs[row*72 + quad*4] = vv;
        }
        __syncthreads();

        // ---- S = Q @ K^T ----
        float s[8][4];
#pragma unroll
        for (int nt = 0; nt < 8; nt++)
#pragma unroll
            for (int i = 0; i < 4; i++) s[nt][i] = 0.f;
#pragma unroll
        for (int nt = 0; nt < 8; nt++) {
            const float* kb = &Ks[(nt*8 + r)*68 + cq];
#pragma unroll
            for (int kc = 0; kc < 8; kc++) {
                uint32_t b0 = __float_as_uint(kb[kc*8]);
                uint32_t b1 = __float_as_uint(kb[kc*8 + 4]);
                mma8(s[nt], qa[kc], b0, b1);
            }
        }

        // ---- causal mask (last two tiles only) ----
        if (t >= nfull) {
            int lim0 = TPAST + q0 + 16*w + r;       // row r0 attends j <= lim0
            int lim1 = lim0 + 8;
#pragma unroll
            for (int nt = 0; nt < 8; nt++) {
                int j = kv0 + nt*8 + cq*2;
                if (j     > lim0) s[nt][0] = -1e30f;
                if (j + 1 > lim0) s[nt][1] = -1e30f;
                if (j     > lim1) s[nt][2] = -1e30f;
                if (j + 1 > lim1) s[nt][3] = -1e30f;
            }
        }

        // ---- online softmax (rows r0 and r0+8; 4-lane groups share a row) ----
        float alpha0, alpha1;
        {
            float mx = -1e30f;
#pragma unroll
            for (int nt = 0; nt < 8; nt++) mx = fmaxf(mx, fmaxf(s[nt][0], s[nt][1]));
            mx = fmaxf(mx, __shfl_xor_sync(0xffffffffu, mx, 1));
            mx = fmaxf(mx, __shfl_xor_sync(0xffffffffu, mx, 2));
            float mn = fmaxf(mi0, mx);
            alpha0 = __expf(mi0 - mn); mi0 = mn;
            float rs = 0.f;
#pragma unroll
            for (int nt = 0; nt < 8; nt++) {
                s[nt][0] = __expf(s[nt][0] - mn);
                s[nt][1] = __expf(s[nt][1] - mn);
                rs += s[nt][0] + s[nt][1];
            }
            rs += __shfl_xor_sync(0xffffffffu, rs, 1);
            rs += __shfl_xor_sync(0xffffffffu, rs, 2);
            li0 = li0 * alpha0 + rs;
        }
        {
            float mx = -1e30f;
#pragma unroll
            for (int nt = 0; nt < 8; nt++) mx = fmaxf(mx, fmaxf(s[nt][2], s[nt][3]));
            mx = fmaxf(mx, __shfl_xor_sync(0xffffffffu, mx, 1));
            mx = fmaxf(mx, __shfl_xor_sync(0xffffffffu, mx, 2));
            float mn = fmaxf(mi1, mx);
            alpha1 = __expf(mi1 - mn); mi1 = mn;
            float rs = 0.f;
#pragma unroll
            for (int nt = 0; nt < 8; nt++) {
                s[nt][2] = __expf(s[nt][2] - mn);
                s[nt][3] = __expf(s[nt][3] - mn);
                rs += s[nt][2] + s[nt][3];
            }
            rs += __shfl_xor_sync(0xffffffffu, rs, 1);
            rs += __shfl_xor_sync(0xffffffffu, rs, 2);
            li1 = li1 * alpha1 + rs;
        }

        // rescale running O
#pragma unroll
        for (int nt = 0; nt < 8; nt++) {
            o[nt][0] *= alpha0; o[nt][1] *= alpha0;
            o[nt][2] *= alpha1; o[nt][3] *= alpha1;
        }

        // ---- store P (tf32) to warp-private region of QP ----
        {
            int m = 16*w + r;
#pragma unroll
            for (int nt = 0; nt < 8; nt++) {
                float2 p0 = make_float2(__uint_as_float(f2tf(s[nt][0])),
                                        __uint_as_float(f2tf(s[nt][1])));
                float2 p1 = make_float2(__uint_as_float(f2tf(s[nt][2])),
                                        __uint_as_float(f2tf(s[nt][3])));
                *(float2*)&QP[m*68     + nt*8 + cq*2] = p0;
                *(float2*)&QP[(m+8)*68 + nt*8 + cq*2] = p1;
            }
        }
        __syncwarp();

        // ---- O += P @ V ----
        {
            int m = 16*w + r;
#pragma unroll
            for (int kc = 0; kc < 8; kc++) {
                uint32_t pa[4];
                pa[0] = __float_as_uint(QP[m*68     + kc*8 + cq]);
                pa[1] = __float_as_uint(QP[(m+8)*68 + kc*8 + cq]);
                pa[2] = __float_as_uint(QP[m*68     + kc*8 + cq + 4]);
                pa[3] = __float_as_uint(QP[(m+8)*68 + kc*8 + cq + 4]);
                const float* vb = &Vs[(kc*8 + cq)*72 + r];
#pragma unroll
                for (int nt = 0; nt < 8; nt++) {
                    uint32_t b0 = __float_as_uint(vb[nt*8]);
                    uint32_t b1 = __float_as_uint(vb[4*72 + nt*8]);
                    mma8(o[nt], pa, b0, b1);
                }
            }
        }
        __syncwarp();
    }

    // ---- normalize + write O ----
    {
        float inv0 = 1.0f / li0, inv1 = 1.0f / li1;
        int qg = b*TQ + q0 + 16*w + r;
        float* dst0 = g_attn + (size_t)qg*DM + (h << 6);
        float* dst1 = dst0 + 8*DM;
#pragma unroll
        for (int nt = 0; nt < 8; nt++) {
            *(float2*)&dst0[nt*8 + cq*2] =
                make_float2(o[nt][0]*inv0, o[nt][1]*inv0);
            *(float2*)&dst1[nt*8 + cq*2] =
                make_float2(o[nt][2]*inv1, o[nt][3]*inv1);
        }
    }
}

// ---------------------------------------------------------------------------
extern "C" void kernel_launch(void* const* d_in, const int* in_sizes, int n_in,
                              void* d_out, int out_size) {
    const float* query  = (const float*)d_in[0];
    const float* key    = (const float*)d_in[1];
    const float* value  = (const float*)d_in[2];
    const float* past_K = (const float*)d_in[3];
    const float* past_V = (const float*)d_in[4];
    // d_in[5] = mask (causal; analytic)
    const float* Wq = (const float*)d_in[6];
    const float* bq = (const float*)d_in[7];
    const float* Wk = (const float*)d_in[8];
    const float* bk = (const float*)d_in[9];
    const float* Wv = (const float*)d_in[10];
    const float* bv = (const float*)d_in[11];
    const float* Wo = (const float*)d_in[12];
    const float* bo = (const float*)d_in[13];

    float* out = (float*)d_out;

    float *gQ, *gAttn, *gK, *gV;
    cudaGetSymbolAddress((void**)&gQ,    g_Q);
    cudaGetSymbolAddress((void**)&gAttn, g_attn);
    cudaGetSymbolAddress((void**)&gK,    g_K);
    cudaGetSymbolAddress((void**)&gV,    g_V);

    float* outK;
    float* outV;
    if ((size_t)out_size >= OUT_TOTAL) {
        outK = out + OUT_O_ELEMS;
        outV = outK + OUT_KV_ELEMS;
    } else {
        outK = gK;
        outV = gV;
    }

    // Unconditional (no static guards per harness contract); host-side,
    // idempotent, capture-safe.
    const int GEMM_SMEM  = 16384 * (int)sizeof(float);   // 64 KB
    const int FLASH_SMEM = (128*68 + 64*68 + 64*72) * (int)sizeof(float); // 70,656 B
    cudaFuncSetAttribute(gemm_tf32,
                         cudaFuncAttributeMaxDynamicSharedMemorySize, GEMM_SMEM);
    cudaFuncSetAttribute(flash_tf32,
                         cudaFuncAttributeMaxDynamicSharedMemorySize, FLASH_SMEM);

    // 1. KV-cache concat (past part)
    {
        int total4 = BB*HH*TPAST*64/4;
        copy_past_kernel<<<(total4 + 255)/256, 256>>>(past_K, past_V, outK, outV);
    }

    // 2. Projections (epilogues fuse head reshape / cache concat / q-scale)
    dim3 gg(DM/128, MROWS/128);
    gemm_tf32<<<gg, 256, GEMM_SMEM>>>(query, Wq, bq, gQ,   0);
    gemm_tf32<<<gg, 256, GEMM_SMEM>>>(key,   Wk, bk, outK, 1);
    gemm_tf32<<<gg, 256, GEMM_SMEM>>>(value, Wv, bv, outV, 1);

    // 3. Attention
    flash_tf32<<<dim3(TQ/128, HH, BB), 256, FLASH_SMEM>>>(outK, outV);

    // 4. Output projection
    gemm_tf32<<<gg, 256, GEMM_SMEM>>>(gAttn, Wo, bo, out, 2);
}

// round 4
// speedup vs baseline: 6.2941x; 1.9737x over previous
#include <cuda_runtime.h>
#include <cuda_fp16.h>
#include <stdint.h>

// Problem constants
#define BB     2
#define HH     16
#define TQ     2048
#define TPAST  2048
#define TKV    4096
#define DM     1024
#define MROWS  (BB*TQ)          // 4096

#define OUT_O_ELEMS  ((size_t)MROWS*DM)            // 4,194,304
#define OUT_KV_ELEMS ((size_t)BB*HH*TKV*64)        // 8,388,608
#define OUT_TOTAL    (OUT_O_ELEMS + 2*OUT_KV_ELEMS)

// Scratch (device globals; allocation inside kernel_launch is forbidden)
__device__ __half g_Qh[BB*HH*TQ*64];     // Q half, [B,H,TQ,64], pre-scaled 1/8
__device__ __half g_Kh[BB*HH*TKV*64];    // K half concat
__device__ __half g_Vh[BB*HH*TKV*64];    // V half concat
__device__ float  g_attn[MROWS*DM];      // attention output [B*TQ, D] f32
__device__ float  g_K[BB*HH*TKV*64];     // fallback f32 KV if d_out small
__device__ float  g_V[BB*HH*TKV*64];

// ---------------------------------------------------------------------------
// PTX helpers
// ---------------------------------------------------------------------------
__device__ __forceinline__ uint32_t pack2(float a, float b) {
    __half2 h = __floats2half2_rn(a, b);
    return *reinterpret_cast<uint32_t*>(&h);
}

__device__ __forceinline__ void mma16(float* c, const uint32_t* a,
                                      uint32_t b0, uint32_t b1) {
    asm volatile(
        "mma.sync.aligned.m16n8k16.row.col.f32.f16.f16.f32 "
        "{%0,%1,%2,%3},{%4,%5,%6,%7},{%8,%9},{%0,%1,%2,%3};"
        : "+f"(c[0]), "+f"(c[1]), "+f"(c[2]), "+f"(c[3])
        : "r"(a[0]), "r"(a[1]), "r"(a[2]), "r"(a[3]), "r"(b0), "r"(b1));
}

__device__ __forceinline__ void ldm4(uint32_t* d, uint32_t addr) {
    asm volatile("ldmatrix.sync.aligned.m8n8.x4.shared.b16 {%0,%1,%2,%3}, [%4];"
        : "=r"(d[0]), "=r"(d[1]), "=r"(d[2]), "=r"(d[3]) : "r"(addr));
}
__device__ __forceinline__ void ldm4t(uint32_t* d, uint32_t addr) {
    asm volatile("ldmatrix.sync.aligned.m8n8.x4.trans.shared.b16 {%0,%1,%2,%3}, [%4];"
        : "=r"(d[0]), "=r"(d[1]), "=r"(d[2]), "=r"(d[3]) : "r"(addr));
}

// ---------------------------------------------------------------------------
// past_K / past_V -> concat destination (f32 KV cache output + half copies)
// ---------------------------------------------------------------------------
__global__ void copy_past_kernel(const float* __restrict__ pk,
                                 const float* __restrict__ pv,
                                 float* __restrict__ outK,
                                 float* __restrict__ outV,
                                 __half* __restrict__ outKh,
                                 __half* __restrict__ outVh) {
    int idx = blockIdx.x * blockDim.x + threadIdx.x;   // float4 index
    const int total = BB*HH*TPAST*64/4;
    if (idx >= total) return;
    const int per_bh = TPAST*64/4;
    int bh  = idx / per_bh;
    int rem = idx - bh*per_bh;
    float4 k4 = ((const float4*)pk)[idx];
    float4 v4 = ((const float4*)pv)[idx];
    size_t o = (size_t)bh*(TKV*64/4) + rem;
    ((float4*)outK)[o] = k4;
    ((float4*)outV)[o] = v4;
    ((uint2*)outKh)[o] = make_uint2(pack2(k4.x, k4.y), pack2(k4.z, k4.w));
    ((uint2*)outVh)[o] = make_uint2(pack2(v4.x, v4.y), pack2(v4.z, v4.w));
}

// ---------------------------------------------------------------------------
// FP16 tensor-core NT GEMM: C[m,n] = sum_k A[m,k]*W[n,k] + bias[n]
// CTA 128x128, BK=32, 256 thr (8 warps), warp 64x32 via m16n8k16.
// Double-buffered smem (half, pad 40), reg-staged global loads w/ f32->f16 cvt.
// Modes: 0 = Q half head layout (*0.125), 1 = KV concat (f32 + half),
//        2 = plain f32 [M,N].
// ---------------------------------------------------------------------------
__global__ __launch_bounds__(256) void gemm_h(const float* __restrict__ A,
                                              const float* __restrict__ W,
                                              const float* __restrict__ bias,
                                              float* __restrict__ Cf,
                                              __half* __restrict__ Ch,
                                              int mode) {
    __shared__ __align__(16) __half gsm[2*10240];  // buf{0,1}: A[128*40] W[128*40]

    const int tid  = threadIdx.x;
    const int lane = tid & 31;
    const int wid  = tid >> 5;
    const int wm   = wid & 1;
    const int wn   = wid >> 1;
    const int m0   = blockIdx.y * 128;
    const int n0   = blockIdx.x * 128;
    const int r    = lane >> 2;
    const int cq   = lane & 3;

    const int srow  = tid >> 3;     // +32p
    const int squad = tid & 7;

    // ldmatrix lane offsets
    const int lra = (lane & 7) + ((lane >> 3) & 1)*8;   // A-style row
    const int lca = (lane >> 4)*8;                      // A-style col oct
    const int lrb = (lane & 7) + (lane >> 4)*8;         // B-style row
    const int lcb = ((lane >> 3) & 1)*8;                // B-style col oct

    uint32_t smb = (uint32_t)__cvta_generic_to_shared(gsm);

    const float* Ag = A + (size_t)m0*DM;
    const float* Wg = W + (size_t)n0*DM;

    float4 areg[4], wreg[4];
#define LOADSTAGE(kt)                                                           \
    {                                                                           \
        int kb = (kt)*32 + squad*4;                                             \
        _Pragma("unroll")                                                       \
        for (int p = 0; p < 4; p++) {                                           \
            int row = srow + p*32;                                              \
            areg[p] = *(const float4*)&Ag[(size_t)row*DM + kb];                 \
            wreg[p] = *(const float4*)&Wg[(size_t)row*DM + kb];                 \
        }                                                                       \
    }
#define STORESTAGE(buf)                                                         \
    {                                                                           \
        __half* Ab = gsm + (buf)*10240;                                         \
        __half* Wb = Ab + 5120;                                                 \
        _Pragma("unroll")                                                       \
        for (int p = 0; p < 4; p++) {                                           \
            int row = srow + p*32;                                              \
            *(uint2*)&Ab[row*40 + squad*4] =                                    \
                make_uint2(pack2(areg[p].x, areg[p].y),                         \
                           pack2(areg[p].z, areg[p].w));                        \
            *(uint2*)&Wb[row*40 + squad*4] =                                    \
                make_uint2(pack2(wreg[p].x, wreg[p].y),                         \
                           pack2(wreg[p].z, wreg[p].w));                        \
        }                                                                       \
    }

    float acc[4][4][4];
#pragma unroll
    for (int mt = 0; mt < 4; mt++)
#pragma unroll
        for (int nt = 0; nt < 4; nt++)
#pragma unroll
            for (int i = 0; i < 4; i++) acc[mt][nt][i] = 0.f;

    LOADSTAGE(0);
    STORESTAGE(0);
    __syncthreads();

    for (int kt = 0; kt < 32; kt++) {
        if (kt + 1 < 32) LOADSTAGE(kt + 1);    // overlaps compute

        uint32_t ab = smb + (uint32_t)((kt & 1) * 20480);
        uint32_t wb = ab + 10240;
#pragma unroll
        for (int kc = 0; kc < 2; kc++) {
            uint32_t af[4][4], bf[2][4];
#pragma unroll
            for (int mt = 0; mt < 4; mt++)
                ldm4(af[mt], ab + (uint32_t)(((wm*64 + mt*16 + lra)*40
                                              + kc*16 + lca)*2));
#pragma unroll
            for (int np = 0; np < 2; np++)
                ldm4(bf[np], wb + (uint32_t)(((wn*32 + np*16 + lrb)*40
                                              + kc*16 + lcb)*2));
#pragma unroll
            for (int mt = 0; mt < 4; mt++)
#pragma unroll
                for (int np = 0; np < 2; np++) {
                    mma16(acc[mt][2*np],   af[mt], bf[np][0], bf[np][1]);
                    mma16(acc[mt][2*np+1], af[mt], bf[np][2], bf[np][3]);
                }
        }
        if (kt + 1 < 32) STORESTAGE((kt + 1) & 1);
        __syncthreads();
    }
#undef LOADSTAGE
#undef STORESTAGE

    // ---- epilogue (c-frag: c0,c1 = row r; c2,c3 = row r+8; cols cq*2,+1) ----
#pragma unroll
    for (int mt = 0; mt < 4; mt++) {
#pragma unroll
        for (int hf = 0; hf < 2; hf++) {
            int m  = m0 + wm*64 + mt*16 + r + hf*8;
            int bb = m / TQ;
            int tq = m - bb*TQ;
#pragma unroll
            for (int nt = 0; nt < 4; nt++) {
                int n = n0 + wn*32 + nt*8 + cq*2;
                float2 bi = *(const float2*)&bias[n];
                float v0 = acc[mt][nt][hf*2 + 0] + bi.x;
                float v1 = acc[mt][nt][hf*2 + 1] + bi.y;
                int hh = n >> 6, d = n & 63;
                if (mode == 0) {
                    *(uint32_t*)&Ch[(((size_t)(bb*HH + hh)*TQ + tq) << 6) + d] =
                        pack2(v0*0.125f, v1*0.125f);
                } else if (mode == 1) {
                    size_t off = (((size_t)(bb*HH + hh)*TKV + TPAST + tq) << 6) + d;
                    *(float2*)&Cf[off] = make_float2(v0, v1);
                    *(uint32_t*)&Ch[off] = pack2(v0, v1);
                } else {
                    *(float2*)&Cf[(size_t)m*DM + n] = make_float2(v0, v1);
                }
            }
        }
    }
}

// ---------------------------------------------------------------------------
// FP16 flash attention. CTA = 128 q rows x (b,h); 8 warps, warp = 16 q rows x
// full 64 j x 64 d. Q fragments in registers all loop; K via ldmatrix (n-major),
// V via ldmatrix.trans; P stays in registers (fp16 A-frag pairs == S C-frag
// pairs). Double-buffered K/V smem, one sync per tile.
// ---------------------------------------------------------------------------
__global__ __launch_bounds__(256) void flash_h(const __half* __restrict__ Kh,
                                               const __half* __restrict__ Vh) {
    __shared__ __align__(16) __half fsm[2*9216];  // buf: K[64*72] V[64*72]; Q aliases

    const int tid  = threadIdx.x;
    const int lane = tid & 31;
    const int w    = tid >> 5;
    const int r    = lane >> 2;
    const int cq   = lane & 3;
    const int q0   = blockIdx.x * 128;
    const int h    = blockIdx.y;
    const int b    = blockIdx.z;

    const __half* Qg = g_Qh + (((size_t)(b*HH + h)*TQ + q0) << 6);
    const __half* Kg = Kh + (((size_t)(b*HH + h)*TKV) << 6);
    const __half* Vg = Vh + (((size_t)(b*HH + h)*TKV) << 6);

    const int srow = tid >> 3;
    const int soct = tid & 7;

    const int lra = (lane & 7) + ((lane >> 3) & 1)*8;
    const int lca = (lane >> 4)*8;
    const int lrb = (lane & 7) + (lane >> 4)*8;
    const int lcb = ((lane >> 3) & 1)*8;

    uint32_t smb = (uint32_t)__cvta_generic_to_shared(fsm);

    uint4 kr[2], vr[2];
#define LOADKV(t)                                                               \
    {                                                                           \
        int j0 = (t)*64;                                                        \
        _Pragma("unroll")                                                       \
        for (int p = 0; p < 2; p++) {                                           \
            int row = j0 + srow + p*32;                                         \
            kr[p] = *(const uint4*)&Kg[((size_t)row << 6) + soct*8];            \
            vr[p] = *(const uint4*)&Vg[((size_t)row << 6) + soct*8];            \
        }                                                                       \
    }
#define STOREKV(buf)                                                            \
    {                                                                           \
        __half* Kb = fsm + (buf)*9216;                                          \
        __half* Vb = Kb + 4608;                                                 \
        _Pragma("unroll")                                                       \
        for (int p = 0; p < 2; p++) {                                           \
            int row = srow + p*32;                                              \
            *(uint4*)&Kb[row*72 + soct*8] = kr[p];                              \
            *(uint4*)&Vb[row*72 + soct*8] = vr[p];                              \
        }                                                                       \
    }

    LOADKV(0);

    // Q tile -> smem (half), extract fragments
#pragma unroll
    for (int p = 0; p < 4; p++) {
        int row = srow + p*32;
        *(uint4*)&fsm[row*72 + soct*8] = *(const uint4*)&Qg[((size_t)row << 6) + soct*8];
    }
    __syncthreads();
    uint32_t qa[4][4];
#pragma unroll
    for (int kc = 0; kc < 4; kc++)
        ldm4(qa[kc], smb + (uint32_t)(((16*w + lra)*72 + kc*16 + lca)*2));
    __syncthreads();   // Q smem dead

    STOREKV(0);
    __syncthreads();

    float o[8][4];
#pragma unroll
    for (int nt = 0; nt < 8; nt++)
#pragma unroll
        for (int i = 0; i < 4; i++) o[nt][i] = 0.f;
    float mi0 = -1e30f, mi1 = -1e30f, li0 = 0.f, li1 = 0.f;

    const int nfull  = (TPAST + q0) >> 6;
    const int ntiles = nfull + 2;

    for (int t = 0; t < ntiles; t++) {
        if (t + 1 < ntiles) LOADKV(t + 1);

        const int kv0 = t * 64;
        uint32_t kb = smb + (uint32_t)((t & 1) * 18432);
        uint32_t vb = kb + 9216;

        // ---- S = Q @ K^T ----
        float s[8][4];
#pragma unroll
        for (int nt = 0; nt < 8; nt++)
#pragma unroll
            for (int i = 0; i < 4; i++) s[nt][i] = 0.f;
#pragma unroll
        for (int kc = 0; kc < 4; kc++)
#pragma unroll
            for (int np = 0; np < 4; np++) {
                uint32_t bf[4];
                ldm4(bf, kb + (uint32_t)(((np*16 + lrb)*72 + kc*16 + lcb)*2));
                mma16(s[2*np],   qa[kc], bf[0], bf[1]);
                mma16(s[2*np+1], qa[kc], bf[2], bf[3]);
            }

        // ---- causal mask (last two tiles) ----
        if (t >= nfull) {
            int lim0 = TPAST + q0 + 16*w + r;
            int lim1 = lim0 + 8;
#pragma unroll
            for (int nt = 0; nt < 8; nt++) {
                int j = kv0 + nt*8 + cq*2;
                if (j     > lim0) s[nt][0] = -1e30f;
                if (j + 1 > lim0) s[nt][1] = -1e30f;
                if (j     > lim1) s[nt][2] = -1e30f;
                if (j + 1 > lim1) s[nt][3] = -1e30f;
            }
        }

        // ---- online softmax (rows r0, r0+8; 4-lane groups share a row) ----
        float alpha0, alpha1;
        {
            float mx = -1e30f;
#pragma unroll
            for (int nt = 0; nt < 8; nt++) mx = fmaxf(mx, fmaxf(s[nt][0], s[nt][1]));
            mx = fmaxf(mx, __shfl_xor_sync(0xffffffffu, mx, 1));
            mx = fmaxf(mx, __shfl_xor_sync(0xffffffffu, mx, 2));
            float mn = fmaxf(mi0, mx);
            alpha0 = __expf(mi0 - mn); mi0 = mn;
            float rs = 0.f;
#pragma unroll
            for (int nt = 0; nt < 8; nt++) {
                s[nt][0] = __expf(s[nt][0] - mn);
                s[nt][1] = __expf(s[nt][1] - mn);
                rs += s[nt][0] + s[nt][1];
            }
            rs += __shfl_xor_sync(0xffffffffu, rs, 1);
            rs += __shfl_xor_sync(0xffffffffu, rs, 2);
            li0 = li0 * alpha0 + rs;
        }
        {
            float mx = -1e30f;
#pragma unroll
            for (int nt = 0; nt < 8; nt++) mx = fmaxf(mx, fmaxf(s[nt][2], s[nt][3]));
            mx = fmaxf(mx, __shfl_xor_sync(0xffffffffu, mx, 1));
            mx = fmaxf(mx, __shfl_xor_sync(0xffffffffu, mx, 2));
            float mn = fmaxf(mi1, mx);
            alpha1 = __expf(mi1 - mn); mi1 = mn;
            float rs = 0.f;
#pragma unroll
            for (int nt = 0; nt < 8; nt++) {
                s[nt][2] = __expf(s[nt][2] - mn);
                s[nt][3] = __expf(s[nt][3] - mn);
                rs += s[nt][2] + s[nt][3];
            }
            rs += __shfl_xor_sync(0xffffffffu, rs, 1);
            rs += __shfl_xor_sync(0xffffffffu, rs, 2);
            li1 = li1 * alpha1 + rs;
        }

#pragma unroll
        for (int nt = 0; nt < 8; nt++) {
            o[nt][0] *= alpha0; o[nt][1] *= alpha0;
            o[nt][2] *= alpha1; o[nt][3] *= alpha1;
        }

        // ---- O += P @ V  (P a-frags are register repacks of S c-frags) ----
#pragma unroll
        for (int kc = 0; kc < 4; kc++) {
            uint32_t pa[4];
            pa[0] = pack2(s[2*kc][0],   s[2*kc][1]);
            pa[1] = pack2(s[2*kc][2],   s[2*kc][3]);
            pa[2] = pack2(s[2*kc+1][0], s[2*kc+1][1]);
            pa[3] = pack2(s[2*kc+1][2], s[2*kc+1][3]);
#pragma unroll
            for (int np = 0; np < 4; np++) {
                uint32_t bf[4];
                ldm4t(bf, vb + (uint32_t)(((kc*16 + lra)*72 + np*16 + lca)*2));
                mma16(o[2*np],   pa, bf[0], bf[1]);
                mma16(o[2*np+1], pa, bf[2], bf[3]);
            }
        }

        if (t + 1 < ntiles) STOREKV((t + 1) & 1);
        __syncthreads();
    }
#undef LOADKV
#undef STOREKV

    // ---- normalize + write O ----
    {
        float inv0 = 1.0f / li0, inv1 = 1.0f / li1;
        int qg = b*TQ + q0 + 16*w + r;
        float* dst0 = g_attn + (size_t)qg*DM + (h << 6);
        float* dst1 = dst0 + 8*DM;
#pragma unroll
        for (int nt = 0; nt < 8; nt++) {
            *(float2*)&dst0[nt*8 + cq*2] =
                make_float2(o[nt][0]*inv0, o[nt][1]*inv0);
            *(float2*)&dst1[nt*8 + cq*2] =
                make_float2(o[nt][2]*inv1, o[nt][3]*inv1);
        }
    }
}

// ---------------------------------------------------------------------------
extern "C" void kernel_launch(void* const* d_in, const int* in_sizes, int n_in,
                              void* d_out, int out_size) {
    const float* query  = (const float*)d_in[0];
    const float* key    = (const float*)d_in[1];
    const float* value  = (const float*)d_in[2];
    const float* past_K = (const float*)d_in[3];
    const float* past_V = (const float*)d_in[4];
    // d_in[5] = mask (causal; analytic)
    const float* Wq = (const float*)d_in[6];
    const float* bq = (const float*)d_in[7];
    const float* Wk = (const float*)d_in[8];
    const float* bk = (const float*)d_in[9];
    const float* Wv = (const float*)d_in[10];
    const float* bv = (const float*)d_in[11];
    const float* Wo = (const float*)d_in[12];
    const float* bo = (const float*)d_in[13];

    float* out = (float*)d_out;

    __half *gQh, *gKh, *gVh;
    float *gAttn, *gK, *gV;
    cudaGetSymbolAddress((void**)&gQh,   g_Qh);
    cudaGetSymbolAddress((void**)&gKh,   g_Kh);
    cudaGetSymbolAddress((void**)&gVh,   g_Vh);
    cudaGetSymbolAddress((void**)&gAttn, g_attn);
    cudaGetSymbolAddress((void**)&gK,    g_K);
    cudaGetSymbolAddress((void**)&gV,    g_V);

    float* outK;
    float* outV;
    if ((size_t)out_size >= OUT_TOTAL) {
        outK = out + OUT_O_ELEMS;
        outV = outK + OUT_KV_ELEMS;
    } else {
        outK = gK;
        outV = gV;
    }

    // 1. KV-cache concat (past part), f32 + half copies
    {
        int total4 = BB*HH*TPAST*64/4;
        copy_past_kernel<<<(total4 + 255)/256, 256>>>(past_K, past_V,
                                                      outK, outV, gKh, gVh);
    }

    // 2. Projections (epilogues fuse head reshape / cache concat / q-scale)
    dim3 gg(DM/128, MROWS/128);
    gemm_h<<<gg, 256>>>(query, Wq, bq, nullptr, gQh, 0);
    gemm_h<<<gg, 256>>>(key,   Wk, bk, outK,    gKh, 1);
    gemm_h<<<gg, 256>>>(value, Wv, bv, outV,    gVh, 1);

    // 3. Attention (reads half Q/K/V)
    flash_h<<<dim3(TQ/128, HH, BB), 256>>>(gKh, gVh);

    // 4. Output projection
    gemm_h<<<gg, 256>>>(gAttn, Wo, bo, out, nullptr, 2);
}

// round 6
// speedup vs baseline: 6.3526x; 1.0093x over previous
#include <cuda_runtime.h>
#include <cuda_fp16.h>
#include <stdint.h>

// Problem constants
#define BB     2
#define HH     16
#define TQ     2048
#define TPAST  2048
#define TKV    4096
#define DM     1024
#define MROWS  (BB*TQ)          // 4096

#define OUT_O_ELEMS  ((size_t)MROWS*DM)            // 4,194,304
#define OUT_KV_ELEMS ((size_t)BB*HH*TKV*64)        // 8,388,608
#define OUT_TOTAL    (OUT_O_ELEMS + 2*OUT_KV_ELEMS)

// Scratch (device globals; allocation inside kernel_launch is forbidden)
__device__ __half g_xq[MROWS*DM];        // half copies of GEMM inputs
__device__ __half g_xk[MROWS*DM];
__device__ __half g_xv[MROWS*DM];
__device__ __half g_wq[DM*DM];
__device__ __half g_wk[DM*DM];
__device__ __half g_wv[DM*DM];
__device__ __half g_wo[DM*DM];
__device__ __half g_Qh[BB*HH*TQ*64];     // projected Q half, pre-scaled 1/8
__device__ __half g_Kh[BB*HH*TKV*64];    // K half concat
__device__ __half g_Vh[BB*HH*TKV*64];    // V half concat
__device__ __half g_attnh[MROWS*DM];     // attention output half [B*TQ, D]
__device__ float  g_K[BB*HH*TKV*64];     // fallback f32 KV if d_out small
__device__ float  g_V[BB*HH*TKV*64];

// ---------------------------------------------------------------------------
// PTX helpers
// ---------------------------------------------------------------------------
__device__ __forceinline__ uint32_t pack2(float a, float b) {
    __half2 h = __floats2half2_rn(a, b);
    return *reinterpret_cast<uint32_t*>(&h);
}

__device__ __forceinline__ void mma16(float* c, const uint32_t* a,
                                      uint32_t b0, uint32_t b1) {
    asm volatile(
        "mma.sync.aligned.m16n8k16.row.col.f32.f16.f16.f32 "
        "{%0,%1,%2,%3},{%4,%5,%6,%7},{%8,%9},{%0,%1,%2,%3};"
        : "+f"(c[0]), "+f"(c[1]), "+f"(c[2]), "+f"(c[3])
        : "r"(a[0]), "r"(a[1]), "r"(a[2]), "r"(a[3]), "r"(b0), "r"(b1));
}

__device__ __forceinline__ void ldm4(uint32_t* d, uint32_t addr) {
    asm volatile("ldmatrix.sync.aligned.m8n8.x4.shared.b16 {%0,%1,%2,%3}, [%4];"
        : "=r"(d[0]), "=r"(d[1]), "=r"(d[2]), "=r"(d[3]) : "r"(addr));
}
__device__ __forceinline__ void ldm4t(uint32_t* d, uint32_t addr) {
    asm volatile("ldmatrix.sync.aligned.m8n8.x4.trans.shared.b16 {%0,%1,%2,%3}, [%4];"
        : "=r"(d[0]), "=r"(d[1]), "=r"(d[2]), "=r"(d[3]) : "r"(addr));
}
__device__ __forceinline__ void cp16(uint32_t s, const void* g) {
    asm volatile("cp.async.cg.shared.global [%0], [%1], 16;" :: "r"(s), "l"(g));
}
__device__ __forceinline__ void cp_commit() { asm volatile("cp.async.commit_group;"); }
template<int N> __device__ __forceinline__ void cp_wait() {
    asm volatile("cp.async.wait_group %0;" :: "n"(N));
}

// ---------------------------------------------------------------------------
// f32 -> f16 bulk conversion of GEMM inputs (7 tensors via blockIdx.y)
// ---------------------------------------------------------------------------
__global__ void prep_convert(const float* __restrict__ q,  const float* __restrict__ k,
                             const float* __restrict__ v,  const float* __restrict__ wq,
                             const float* __restrict__ wk, const float* __restrict__ wv,
                             const float* __restrict__ wo) {
    const float* src; __half* dst; int n4;
    switch (blockIdx.y) {
        case 0: src = q;  dst = g_xq; n4 = MROWS*DM/4; break;
        case 1: src = k;  dst = g_xk; n4 = MROWS*DM/4; break;
        case 2: src = v;  dst = g_xv; n4 = MROWS*DM/4; break;
        case 3: src = wq; dst = g_wq; n4 = DM*DM/4;    break;
        case 4: src = wk; dst = g_wk; n4 = DM*DM/4;    break;
        case 5: src = wv; dst = g_wv; n4 = DM*DM/4;    break;
        default:src = wo; dst = g_wo; n4 = DM*DM/4;    break;
    }
    int i = blockIdx.x * blockDim.x + threadIdx.x;
    if (i >= n4) return;
    float4 x = ((const float4*)src)[i];
    ((uint2*)dst)[i] = make_uint2(pack2(x.x, x.y), pack2(x.z, x.w));
}

// ---------------------------------------------------------------------------
// past_K / past_V -> concat destination (f32 KV cache output + half copies)
// ---------------------------------------------------------------------------
__global__ void copy_past_kernel(const float* __restrict__ pk,
                                 const float* __restrict__ pv,
                                 float* __restrict__ outK,
                                 float* __restrict__ outV) {
    int idx = blockIdx.x * blockDim.x + threadIdx.x;   // float4 index
    const int total = BB*HH*TPAST*64/4;
    if (idx >= total) return;
    const int per_bh = TPAST*64/4;
    int bh  = idx / per_bh;
    int rem = idx - bh*per_bh;
    float4 k4 = ((const float4*)pk)[idx];
    float4 v4 = ((const float4*)pv)[idx];
    size_t o = (size_t)bh*(TKV*64/4) + rem;
    ((float4*)outK)[o] = k4;
    ((float4*)outV)[o] = v4;
    ((uint2*)g_Kh)[o] = make_uint2(pack2(k4.x, k4.y), pack2(k4.z, k4.w));
    ((uint2*)g_Vh)[o] = make_uint2(pack2(v4.x, v4.y), pack2(v4.z, v4.w));
}

// ---------------------------------------------------------------------------
// FP16 tensor-core NT GEMM: C[m,n] = sum_k A[m,k]*W[n,k] + bias[n]
// All-half inputs. CTA 128x128, BK=32, 256 thr (8 warps), warp 64x32.
// 4-stage cp.async pipeline (wait_group<2>; empty commit at tail keeps the
// pending-group arithmetic uniform so the wait always covers tile kt).
// Modes: 0 = Q half head layout (*0.125), 1 = KV concat (f32 + half),
//        2 = plain f32 [M,N].
// ---------------------------------------------------------------------------
__global__ __launch_bounds__(256) void gemm_h(const __half* __restrict__ A,
                                              const __half* __restrict__ W,
                                              const float* __restrict__ bias,
                                              float* __restrict__ Cf,
                                              __half* __restrict__ Ch,
                                              int mode) {
    extern __shared__ __half gsm[];   // 4 stages x (A 128*40 + W 128*40) halves

    const int tid  = threadIdx.x;
    const int lane = tid & 31;
    const int wid  = tid >> 5;
    const int wm   = wid & 1;
    const int wn   = wid >> 1;
    const int m0   = blockIdx.y * 128;
    const int n0   = blockIdx.x * 128;
    const int r    = lane >> 2;
    const int cq   = lane & 3;

    // ldmatrix lane offsets
    const int lra = (lane & 7) + ((lane >> 3) & 1)*8;
    const int lca = (lane >> 4)*8;
    const int lrb = (lane & 7) + (lane >> 4)*8;
    const int lcb = ((lane >> 3) & 1)*8;

    uint32_t smb = (uint32_t)__cvta_generic_to_shared(gsm);
    const __half* Ag = A + (size_t)m0*DM;
    const __half* Wg = W + (size_t)n0*DM;

    // stage issue: 2 chunks/thread/matrix; chunk c: row=c>>2, col=c&3
#define GISSUE(kt, s)                                                           \
    {                                                                           \
        uint32_t sb = smb + (uint32_t)((s) * 20480);                            \
        _Pragma("unroll")                                                       \
        for (int p = 0; p < 2; p++) {                                           \
            int cc  = tid + p*256;                                              \
            int row = cc >> 2, col = cc & 3;                                    \
            cp16(sb + (uint32_t)(row*80 + col*16),                              \
                 Ag + (size_t)row*DM + (kt)*32 + col*8);                        \
            cp16(sb + (uint32_t)(10240 + row*80 + col*16),                      \
                 Wg + (size_t)row*DM + (kt)*32 + col*8);                        \
        }                                                                       \
        cp_commit();                                                            \
    }

    float acc[4][4][4];
#pragma unroll
    for (int mt = 0; mt < 4; mt++)
#pragma unroll
        for (int nt = 0; nt < 4; nt++)
#pragma unroll
            for (int i = 0; i < 4; i++) acc[mt][nt][i] = 0.f;

    GISSUE(0, 0);
    GISSUE(1, 1);
    GISSUE(2, 2);

    for (int kt = 0; kt < 32; kt++) {
        cp_wait<2>();
        __syncthreads();
        if (kt + 3 < 32) { GISSUE(kt + 3, (kt + 3) & 3); }
        else             { cp_commit(); }   // empty group: keeps wait<2> exact

        uint32_t ab = smb + (uint32_t)((kt & 3) * 20480);
        uint32_t wb = ab + 10240;
#pragma unroll
        for (int kc = 0; kc < 2; kc++) {
            uint32_t af[4][4], bf[2][4];
#pragma unroll
            for (int mt = 0; mt < 4; mt++)
                ldm4(af[mt], ab + (uint32_t)(((wm*64 + mt*16 + lra)*40
                                              + kc*16 + lca)*2));
#pragma unroll
            for (int np = 0; np < 2; np++)
                ldm4(bf[np], wb + (uint32_t)(((wn*32 + np*16 + lrb)*40
                                              + kc*16 + lcb)*2));
#pragma unroll
            for (int mt = 0; mt < 4; mt++)
#pragma unroll
                for (int np = 0; np < 2; np++) {
                    mma16(acc[mt][2*np],   af[mt], bf[np][0], bf[np][1]);
                    mma16(acc[mt][2*np+1], af[mt], bf[np][2], bf[np][3]);
                }
        }
    }
#undef GISSUE

    // ---- epilogue (c-frag: c0,c1 = row r; c2,c3 = row r+8; cols cq*2,+1) ----
#pragma unroll
    for (int mt = 0; mt < 4; mt++) {
#pragma unroll
        for (int hf = 0; hf < 2; hf++) {
            int m  = m0 + wm*64 + mt*16 + r + hf*8;
            int bb = m / TQ;
            int tq = m - bb*TQ;
#pragma unroll
            for (int nt = 0; nt < 4; nt++) {
                int n = n0 + wn*32 + nt*8 + cq*2;
                float2 bi = *(const float2*)&bias[n];
                float v0 = acc[mt][nt][hf*2 + 0] + bi.x;
                float v1 = acc[mt][nt][hf*2 + 1] + bi.y;
                int hh = n >> 6, d = n & 63;
                if (mode == 0) {
                    *(uint32_t*)&Ch[(((size_t)(bb*HH + hh)*TQ + tq) << 6) + d] =
                        pack2(v0*0.125f, v1*0.125f);
                } else if (mode == 1) {
                    size_t off = (((size_t)(bb*HH + hh)*TKV + TPAST + tq) << 6) + d;
                    *(float2*)&Cf[off] = make_float2(v0, v1);
                    *(uint32_t*)&Ch[off] = pack2(v0, v1);
                } else {
                    *(float2*)&Cf[(size_t)m*DM + n] = make_float2(v0, v1);
                }
            }
        }
    }
}

// ---------------------------------------------------------------------------
// FP16 flash attention. CTA = 128 q rows x (b,h); 8 warps, warp = 16 q rows x
// full 64 j x 64 d. Q frags in registers; K via ldmatrix, V via ldmatrix.trans;
// P stays in registers. 4-stage cp.async K/V pipeline (empty commit at tail).
// Reversed q-tile order (longest KV first). Output written as half.
// ---------------------------------------------------------------------------
__global__ __launch_bounds__(256) void flash_h() {
    extern __shared__ __half fsm[];  // Q region 128*72, then 4 stages (K 64*72 + V 64*72)

    const int tid  = threadIdx.x;
    const int lane = tid & 31;
    const int w    = tid >> 5;
    const int r    = lane >> 2;
    const int cq   = lane & 3;
    const int qt   = (int)(gridDim.x - 1 - blockIdx.x);   // reversed: longest first
    const int q0   = qt * 128;
    const int h    = blockIdx.y;
    const int b    = blockIdx.z;

    const __half* Qg = g_Qh + (((size_t)(b*HH + h)*TQ + q0) << 6);
    const __half* Kg = g_Kh + (((size_t)(b*HH + h)*TKV) << 6);
    const __half* Vg = g_Vh + (((size_t)(b*HH + h)*TKV) << 6);

    const int srow = tid >> 3;   // +32p
    const int soct = tid & 7;

    const int lra = (lane & 7) + ((lane >> 3) & 1)*8;
    const int lca = (lane >> 4)*8;
    const int lrb = (lane & 7) + (lane >> 4)*8;
    const int lcb = ((lane >> 3) & 1)*8;

    uint32_t smb = (uint32_t)__cvta_generic_to_shared(fsm);
    const uint32_t kvbase = 18432;   // bytes; Q region is [0, 18432)

    const int nfull  = (TPAST + q0) >> 6;
    const int ntiles = nfull + 2;

    // stage issue: chunk c: row=c>>3, col=c&7 (64 rows x 8 chunks per matrix)
#define FISSUE(t, s)                                                            \
    {                                                                           \
        uint32_t sb = smb + kvbase + (uint32_t)((s) * 18432);                   \
        _Pragma("unroll")                                                       \
        for (int p = 0; p < 2; p++) {                                           \
            int cc  = tid + p*256;                                              \
            int row = cc >> 3, col = cc & 7;                                    \
            size_t g = ((size_t)((t)*64 + row) << 6) + col*8;                   \
            cp16(sb + (uint32_t)(row*144 + col*16),        Kg + g);             \
            cp16(sb + (uint32_t)(9216 + row*144 + col*16), Vg + g);             \
        }                                                                       \
        cp_commit();                                                            \
    }

    FISSUE(0, 0);
    FISSUE(1, 1);
    FISSUE(2, 2);

    // Q tile -> smem (overlaps cp.async latency), extract fragments
#pragma unroll
    for (int p = 0; p < 4; p++) {
        int row = srow + p*32;
        *(uint4*)((char*)fsm + row*144 + soct*16) =
            *(const uint4*)&Qg[((size_t)row << 6) + soct*8];
    }
    __syncthreads();
    uint32_t qa[4][4];
#pragma unroll
    for (int kc = 0; kc < 4; kc++)
        ldm4(qa[kc], smb + (uint32_t)(((16*w + lra)*72 + kc*16 + lca)*2));

    float o[8][4];
#pragma unroll
    for (int nt = 0; nt < 8; nt++)
#pragma unroll
        for (int i = 0; i < 4; i++) o[nt][i] = 0.f;
    float mi0 = -1e30f, mi1 = -1e30f, li0 = 0.f, li1 = 0.f;

    for (int t = 0; t < ntiles; t++) {
        cp_wait<2>();
        __syncthreads();
        if (t + 3 < ntiles) { FISSUE(t + 3, (t + 3) & 3); }
        else                { cp_commit(); }   // empty group: keeps wait<2> exact

        const int kv0 = t * 64;
        uint32_t kb = smb + kvbase + (uint32_t)((t & 3) * 18432);
        uint32_t vb = kb + 9216;

        // ---- S = Q @ K^T ----
        float s[8][4];
#pragma unroll
        for (int nt = 0; nt < 8; nt++)
#pragma unroll
            for (int i = 0; i < 4; i++) s[nt][i] = 0.f;
#pragma unroll
        for (int kc = 0; kc < 4; kc++)
#pragma unroll
            for (int np = 0; np < 4; np++) {
                uint32_t bf[4];
                ldm4(bf, kb + (uint32_t)(((np*16 + lrb)*72 + kc*16 + lcb)*2));
                mma16(s[2*np],   qa[kc], bf[0], bf[1]);
                mma16(s[2*np+1], qa[kc], bf[2], bf[3]);
            }

        // ---- causal mask (last two tiles) ----
        if (t >= nfull) {
            int lim0 = TPAST + q0 + 16*w + r;
            int lim1 = lim0 + 8;
#pragma unroll
            for (int nt = 0; nt < 8; nt++) {
                int j = kv0 + nt*8 + cq*2;
                if (j     > lim0) s[nt][0] = -1e30f;
                if (j + 1 > lim0) s[nt][1] = -1e30f;
                if (j     > lim1) s[nt][2] = -1e30f;
                if (j + 1 > lim1) s[nt][3] = -1e30f;
            }
        }

        // ---- online softmax (rows r0, r0+8; 4-lane groups share a row) ----
        float alpha0, alpha1;
        {
            float mx = -1e30f;
#pragma unroll
            for (int nt = 0; nt < 8; nt++) mx = fmaxf(mx, fmaxf(s[nt][0], s[nt][1]));
            mx = fmaxf(mx, __shfl_xor_sync(0xffffffffu, mx, 1));
            mx = fmaxf(mx, __shfl_xor_sync(0xffffffffu, mx, 2));
            float mn = fmaxf(mi0, mx);
            alpha0 = __expf(mi0 - mn); mi0 = mn;
            float rs = 0.f;
#pragma unroll
            for (int nt = 0; nt < 8; nt++) {
                s[nt][0] = __expf(s[nt][0] - mn);
                s[nt][1] = __expf(s[nt][1] - mn);
                rs += s[nt][0] + s[nt][1];
            }
            rs += __shfl_xor_sync(0xffffffffu, rs, 1);
            rs += __shfl_xor_sync(0xffffffffu, rs, 2);
            li0 = li0 * alpha0 + rs;
        }
        {
            float mx = -1e30f;
#pragma unroll
            for (int nt = 0; nt < 8; nt++) mx = fmaxf(mx, fmaxf(s[nt][2], s[nt][3]));
            mx = fmaxf(mx, __shfl_xor_sync(0xffffffffu, mx, 1));
            mx = fmaxf(mx, __shfl_xor_sync(0xffffffffu, mx, 2));
            float mn = fmaxf(mi1, mx);
            alpha1 = __expf(mi1 - mn); mi1 = mn;
            float rs = 0.f;
#pragma unroll
            for (int nt = 0; nt < 8; nt++) {
                s[nt][2] = __expf(s[nt][2] - mn);
                s[nt][3] = __expf(s[nt][3] - mn);
                rs += s[nt][2] + s[nt][3];
            }
            rs += __shfl_xor_sync(0xffffffffu, rs, 1);
            rs += __shfl_xor_sync(0xffffffffu, rs, 2);
            li1 = li1 * alpha1 + rs;
        }

#pragma unroll
        for (int nt = 0; nt < 8; nt++) {
            o[nt][0] *= alpha0; o[nt][1] *= alpha0;
            o[nt][2] *= alpha1; o[nt][3] *= alpha1;
        }

        // ---- O += P @ V  (P a-frags are register repacks of S c-frags) ----
#pragma unroll
        for (int kc = 0; kc < 4; kc++) {
            uint32_t pa[4];
            pa[0] = pack2(s[2*kc][0],   s[2*kc][1]);
            pa[1] = pack2(s[2*kc][2],   s[2*kc][3]);
            pa[2] = pack2(s[2*kc+1][0], s[2*kc+1][1]);
            pa[3] = pack2(s[2*kc+1][2], s[2*kc+1][3]);
#pragma unroll
            for (int np = 0; np < 4; np++) {
                uint32_t bf[4];
                ldm4t(bf, vb + (uint32_t)(((kc*16 + lra)*72 + np*16 + lca)*2));
                mma16(o[2*np],   pa, bf[0], bf[1]);
                mma16(o[2*np+1], pa, bf[2], bf[3]);
            }
        }
    }
#undef FISSUE

    // ---- normalize + write O (half) ----
    {
        float inv0 = 1.0f / li0, inv1 = 1.0f / li1;
        int qg = b*TQ + q0 + 16*w + r;
        __half* dst0 = g_attnh + (size_t)qg*DM + (h << 6);
        __half* dst1 = dst0 + 8*DM;
#pragma unroll
        for (int nt = 0; nt < 8; nt++) {
            *(uint32_t*)&dst0[nt*8 + cq*2] = pack2(o[nt][0]*inv0, o[nt][1]*inv0);
            *(uint32_t*)&dst1[nt*8 + cq*2] = pack2(o[nt][2]*inv1, o[nt][3]*inv1);
        }
    }
}

// ---------------------------------------------------------------------------
extern "C" void kernel_launch(void* const* d_in, const int* in_sizes, int n_in,
                              void* d_out, int out_size) {
    const float* query  = (const float*)d_in[0];
    const float* key    = (const float*)d_in[1];
    const float* value  = (const float*)d_in[2];
    const float* past_K = (const float*)d_in[3];
    const float* past_V = (const float*)d_in[4];
    // d_in[5] = mask (causal; analytic)
    const float* Wq = (const float*)d_in[6];
    const float* bq = (const float*)d_in[7];
    const float* Wk = (const float*)d_in[8];
    const float* bk = (const float*)d_in[9];
    const float* Wv = (const float*)d_in[10];
    const float* bv = (const float*)d_in[11];
    const float* Wo = (const float*)d_in[12];
    const float* bo = (const float*)d_in[13];

    float* out = (float*)d_out;

    __half *gxq, *gxk, *gxv, *gwq, *gwk, *gwv, *gwo, *gQh, *gAh;
    float *gK, *gV;
    cudaGetSymbolAddress((void**)&gxq, g_xq);
    cudaGetSymbolAddress((void**)&gxk, g_xk);
    cudaGetSymbolAddress((void**)&gxv, g_xv);
    cudaGetSymbolAddress((void**)&gwq, g_wq);
    cudaGetSymbolAddress((void**)&gwk, g_wk);
    cudaGetSymbolAddress((void**)&gwv, g_wv);
    cudaGetSymbolAddress((void**)&gwo, g_wo);
    cudaGetSymbolAddress((void**)&gQh, g_Qh);
    cudaGetSymbolAddress((void**)&gAh, g_attnh);
    cudaGetSymbolAddress((void**)&gK,  g_K);
    cudaGetSymbolAddress((void**)&gV,  g_V);

    __half *gKh, *gVh;
    cudaGetSymbolAddress((void**)&gKh, g_Kh);
    cudaGetSymbolAddress((void**)&gVh, g_Vh);

    float* outK;
    float* outV;
    if ((size_t)out_size >= OUT_TOTAL) {
        outK = out + OUT_O_ELEMS;
        outV = outK + OUT_KV_ELEMS;
    } else {
        outK = gK;
        outV = gV;
    }

    const int GEMM_SMEM  = 4 * 20480;                   // 81,920 B
    const int FLASH_SMEM = 18432 + 4 * 18432;           // 92,160 B
    cudaFuncSetAttribute(gemm_h,
                         cudaFuncAttributeMaxDynamicSharedMemorySize, GEMM_SMEM);
    cudaFuncSetAttribute(flash_h,
                         cudaFuncAttributeMaxDynamicSharedMemorySize, FLASH_SMEM);

    // 0. Convert inputs + weights to half (precision-neutral vs staging cvt)
    prep_convert<<<dim3((MROWS*DM/4 + 255)/256, 7), 256>>>(query, key, value,
                                                           Wq, Wk, Wv, Wo);

    // 1. KV-cache concat (past part), f32 + half copies
    {
        int total4 = BB*HH*TPAST*64/4;
        copy_past_kernel<<<(total4 + 255)/256, 256>>>(past_K, past_V, outK, outV);
    }

    // 2. Projections (epilogues fuse head reshape / cache concat / q-scale)
    dim3 gg(DM/128, MROWS/128);
    gemm_h<<<gg, 256, GEMM_SMEM>>>(gxq, gwq, bq, nullptr, gQh, 0);
    gemm_h<<<gg, 256, GEMM_SMEM>>>(gxk, gwk, bk, outK,    gKh, 1);
    gemm_h<<<gg, 256, GEMM_SMEM>>>(gxv, gwv, bv, outV,    gVh, 1);

    // 3. Attention
    flash_h<<<dim3(TQ/128, HH, BB), 256, FLASH_SMEM>>>();

    // 4. Output projection
    gemm_h<<<gg, 256, GEMM_SMEM>>>(gAh, gwo, bo, out, nullptr, 2);
}